// round 13
// baseline (speedup 1.0000x reference)
#include <cuda_runtime.h>
#include <cuda_fp16.h>
#include <math.h>
#include <stdint.h>

#define BB 2
#define SS 2048
#define EE 256
#define HH 32
#define N_FF 160   // tiles 0..159 (heads 0-9) take the FFMA path

// log2(e)/sqrt(8): folded into the Q fragment / q registers.
#define CSCALE 0.51006972790221780093f

__device__ uint32_t g_attnh[BB * SS * EE / 2];  // attention output, fp16x2 [B,S,E]
__device__ uint4 g_qh[64 * 2048];               // fp16 cos(x+theta): 8 vals (16B) per (bh,s)

// ---- MMA helpers (baseline PTX, compiles for compute_103) ----
__device__ __forceinline__ void mma16816(float d[4],
    uint32_t a0, uint32_t a1, uint32_t a2, uint32_t a3,
    uint32_t b0, uint32_t b1, const float c[4])
{
    asm volatile("mma.sync.aligned.m16n8k16.row.col.f32.f16.f16.f32 "
        "{%0,%1,%2,%3}, {%4,%5,%6,%7}, {%8,%9}, {%10,%11,%12,%13};"
        : "=f"(d[0]), "=f"(d[1]), "=f"(d[2]), "=f"(d[3])
        : "r"(a0), "r"(a1), "r"(a2), "r"(a3), "r"(b0), "r"(b1),
          "f"(c[0]), "f"(c[1]), "f"(c[2]), "f"(c[3]));
}
__device__ __forceinline__ void mma16808h(uint32_t& d0, uint32_t& d1,
    uint32_t a0, uint32_t a1, uint32_t b0)
{
    asm volatile("mma.sync.aligned.m16n8k8.row.col.f16.f16.f16.f16 "
        "{%0,%1}, {%2,%3}, {%4}, {%5,%6};"
        : "=r"(d0), "=r"(d1)
        : "r"(a0), "r"(a1), "r"(b0), "r"(0u), "r"(0u));
}
// ---- f32x2 packed helpers (Blackwell; PTX-only) ----
__device__ __forceinline__ uint64_t f2u(float x, float y) {
    uint64_t r;
    asm("mov.b64 %0, {%1,%2};" : "=l"(r) : "f"(x), "f"(y));
    return r;
}
__device__ __forceinline__ void u2f(uint64_t v, float& x, float& y) {
    asm("mov.b64 {%0,%1}, %2;" : "=f"(x), "=f"(y) : "l"(v));
}
__device__ __forceinline__ uint64_t ffma2(uint64_t a, uint64_t b, uint64_t c) {
    uint64_t d;
    asm("fma.rn.f32x2 %0, %1, %2, %3;" : "=l"(d) : "l"(a), "l"(b), "l"(c));
    return d;
}
__device__ __forceinline__ uint64_t fadd2(uint64_t a, uint64_t b) {
    uint64_t d;
    asm("add.rn.f32x2 %0, %1, %2;" : "=l"(d) : "l"(a), "l"(b));
    return d;
}
__device__ __forceinline__ float ex2f(float x) {
    float r;
    asm("ex2.approx.ftz.f32 %0, %1;" : "=f"(r) : "f"(x));
    return r;
}

// ---------------------------------------------------------------------------
// Prep: q = cos(x + theta) -> fp16 via smem transpose (unchanged from R12).
// ---------------------------------------------------------------------------
__global__ __launch_bounds__(256) void prep_kernel(
    const float* __restrict__ x,
    const float* __restrict__ theta)
{
    __shared__ uint2 tile[32][18];

    const int t   = threadIdx.x;
    const int blk = blockIdx.x;
    const int b   = blk >> 8;
    const int s0  = (blk & 255) << 3;
    float th[8];
#pragma unroll
    for (int d = 0; d < 8; d++) th[d] = __ldg(theta + d);

    const float* xb = x + ((size_t)b * SS + s0) * EE;
#pragma unroll
    for (int l = 0; l < 2; l++) {
        int idx = t + l * 256;
        int row = idx >> 6;
        int c4  = idx & 63;
        float4 v = *reinterpret_cast<const float4*>(xb + (size_t)row * EE + c4 * 4);
        int hf = c4 & 1;
        int db = hf * 4;
        half2 h0 = __floats2half2_rn(__cosf(v.x + th[db + 0]), __cosf(v.y + th[db + 1]));
        half2 h1 = __floats2half2_rn(__cosf(v.z + th[db + 2]), __cosf(v.w + th[db + 3]));
        tile[c4 >> 1][row * 2 + hf] =
            make_uint2(*reinterpret_cast<uint32_t*>(&h0),
                       *reinterpret_cast<uint32_t*>(&h1));
    }
    __syncthreads();
#pragma unroll
    for (int l = 0; l < 2; l++) {
        int idx = t + l * 256;
        int h  = idx >> 4;
        int in = idx & 15;
        uint2 v = tile[h][in];
        uint2* dst = reinterpret_cast<uint2*>(g_qh + (((b << 5) + h) << 11) + s0);
        dst[in] = v;
    }
}

// ---------------------------------------------------------------------------
// Hybrid attention: bids < N_FF use the FFMA/f32x2 path (fma pipe),
// the rest use the warp-MMA path (tensor pipe). Same math, same output fmt.
// ---------------------------------------------------------------------------
union SMem {
    struct {
        uint4    sK[2][128];
        uint32_t sMaskP[2][64];
        uint32_t sVT[2][8][68];
    } mma;
    struct {
        float    kp[2][64][16];    // pair-interleaved fp32 keys
        uint64_t bias2[2][64];     // packed {b0,b1} bias (pre-scaled domain)
        float    red[128][10];     // cross-half reduction buffer
    } ff;
};

__global__ __launch_bounds__(256, 4) void attn_kernel(const int* __restrict__ mask)
{
    __shared__ SMem sm;

    const int tid  = threadIdx.x;
    const int bid  = blockIdx.x;
    const int bh = bid >> 4;
    const int qt = bid & 15;
    const int b  = bh >> 5;
    const int h  = bh & 31;

    if (bid < N_FF) {
        // =================== FFMA / f32x2 path ===================
        const int q_idx = tid & 127;
        const int kh    = tid >> 7;          // key-half (0: keys 0-63, 1: 64-127)

        // q registers: fp16 -> fp32 * CSCALE, duplicated into f32x2
        uint64_t q2[8];
        {
            uint4 qv = g_qh[(bh << 11) + (qt << 7) + q_idx];
            uint32_t qa[4] = {qv.x, qv.y, qv.z, qv.w};
#pragma unroll
            for (int d2 = 0; d2 < 4; d2++) {
                float2 f = __half22float2(*reinterpret_cast<half2*>(&qa[d2]));
                float v0 = f.x * CSCALE, v1 = f.y * CSCALE;
                q2[2 * d2]     = f2u(v0, v0);
                q2[2 * d2 + 1] = f2u(v1, v1);
            }
        }

        uint64_t acc2[8];
#pragma unroll
        for (int d = 0; d < 8; d++) acc2[d] = 0ull;
        uint64_t l2 = 0ull;
        const uint64_t zz = 0ull;

        auto load_chunk_ff = [&](int c, int buf) {
            const int kg = (bh << 11) + (c << 7);
            if (tid < 128) {
                uint4 kv = g_qh[kg + tid];
                uint32_t ka[4] = {kv.x, kv.y, kv.z, kv.w};
                float* dst = &sm.ff.kp[buf][tid >> 1][tid & 1];
#pragma unroll
                for (int d2 = 0; d2 < 4; d2++) {
                    float2 f = __half22float2(*reinterpret_cast<half2*>(&ka[d2]));
                    dst[4 * d2]     = f.x;
                    dst[4 * d2 + 2] = f.y;
                }
            } else if (tid < 192) {
                int u = tid - 128;
                int2 mm = *reinterpret_cast<const int2*>(
                    mask + b * SS + (c << 7) + 2 * u);
                sm.ff.bias2[buf][u] = f2u(mm.x ? 0.f : -30000.f,
                                          mm.y ? 0.f : -30000.f);
            }
        };

        load_chunk_ff(0, 0);
        __syncthreads();

        for (int c = 0; c < 16; c++) {
            const int buf = c & 1;
            if (c < 15) load_chunk_ff(c + 1, buf ^ 1);

#pragma unroll 2
            for (int jj = 0; jj < 32; jj++) {
                int j = kh * 32 + jj;
                const ulonglong2* k8 =
                    reinterpret_cast<const ulonglong2*>(&sm.ff.kp[buf][j][0]);
                ulonglong2 v0 = k8[0];
                ulonglong2 v1 = k8[1];
                ulonglong2 v2 = k8[2];
                ulonglong2 v3 = k8[3];
                uint64_t bp = sm.ff.bias2[buf][j];

                uint64_t sA = ffma2(q2[0], v0.x, bp);
                uint64_t sB = ffma2(q2[4], v2.x, zz);
                sA = ffma2(q2[1], v0.y, sA);  sB = ffma2(q2[5], v2.y, sB);
                sA = ffma2(q2[2], v1.x, sA);  sB = ffma2(q2[6], v3.x, sB);
                sA = ffma2(q2[3], v1.y, sA);  sB = ffma2(q2[7], v3.y, sB);
                uint64_t s = fadd2(sA, sB);
                float s0, s1;
                u2f(s, s0, s1);
                uint64_t p2 = f2u(ex2f(s0), ex2f(s1));
                l2 = fadd2(l2, p2);
                acc2[0] = ffma2(p2, v0.x, acc2[0]);
                acc2[1] = ffma2(p2, v0.y, acc2[1]);
                acc2[2] = ffma2(p2, v1.x, acc2[2]);
                acc2[3] = ffma2(p2, v1.y, acc2[3]);
                acc2[4] = ffma2(p2, v2.x, acc2[4]);
                acc2[5] = ffma2(p2, v2.y, acc2[5]);
                acc2[6] = ffma2(p2, v3.x, acc2[6]);
                acc2[7] = ffma2(p2, v3.y, acc2[7]);
            }
            __syncthreads();
        }

        // collapse f32x2 halves
        float acc[8], l;
        {
            float lx, ly;
            u2f(l2, lx, ly);
            l = lx + ly;
#pragma unroll
            for (int d = 0; d < 8; d++) {
                float x0, x1;
                u2f(acc2[d], x0, x1);
                acc[d] = x0 + x1;
            }
        }
        // reduce the two key-halves (different warps) via smem
        if (kh == 1) {
#pragma unroll
            for (int d = 0; d < 8; d++) sm.ff.red[q_idx][d] = acc[d];
            sm.ff.red[q_idx][8] = l;
        }
        __syncthreads();
        if (kh == 0) {
#pragma unroll
            for (int d = 0; d < 8; d++) acc[d] += sm.ff.red[q_idx][d];
            l += sm.ff.red[q_idx][8];
            float inv = 1.0f / l;
            half2 o0 = __floats2half2_rn(acc[0] * inv, acc[1] * inv);
            half2 o1 = __floats2half2_rn(acc[2] * inv, acc[3] * inv);
            half2 o2 = __floats2half2_rn(acc[4] * inv, acc[5] * inv);
            half2 o3 = __floats2half2_rn(acc[6] * inv, acc[7] * inv);
            int q = (qt << 7) + q_idx;
            uint4 ov = make_uint4(*reinterpret_cast<uint32_t*>(&o0),
                                  *reinterpret_cast<uint32_t*>(&o1),
                                  *reinterpret_cast<uint32_t*>(&o2),
                                  *reinterpret_cast<uint32_t*>(&o3));
            *reinterpret_cast<uint4*>(
                g_attnh + ((size_t)b * SS + q) * 128 + h * 4) = ov;
        }
        return;
    }

    // =================== warp-MMA path (R12, unchanged) ===================
    const int wid  = tid >> 5;
    const int lane = tid & 31;
    const int r = lane >> 2;
    const int m = lane & 3;

    const int qbase = (bh << 11) + (qt << 7) + wid * 16;
    const uint32_t* qw = reinterpret_cast<const uint32_t*>(g_qh + qbase);
    uint32_t a0r = qw[r * 4 + m];
    uint32_t a1r = qw[(r + 8) * 4 + m];
    float2 f0 = __half22float2(*reinterpret_cast<half2*>(&a0r));
    float2 f1 = __half22float2(*reinterpret_cast<half2*>(&a1r));
    half2 s0 = __floats2half2_rn(f0.x * CSCALE, f0.y * CSCALE);
    half2 s1 = __floats2half2_rn(f1.x * CSCALE, f1.y * CSCALE);
    const uint32_t a0 = *reinterpret_cast<uint32_t*>(&s0);
    const uint32_t a1 = *reinterpret_cast<uint32_t*>(&s1);

    float O[4] = {0.f, 0.f, 0.f, 0.f};
    float l_lo = 0.f, l_hi = 0.f;

    auto load_chunk = [&](int c, int buf) {
        const int kg = (bh << 11) + (c << 7);
        if (tid < 128) {
            sm.mma.sK[buf][tid] = g_qh[kg + tid];
            if (tid < 64) {
                int2 mm = *reinterpret_cast<const int2*>(
                    mask + b * SS + (c << 7) + 2 * tid);
                sm.mma.sMaskP[buf][tid] = (mm.x ? 0x0000FFFFu : 0u) |
                                          (mm.y ? 0xFFFF0000u : 0u);
            }
        } else {
            int u  = (tid - 128) >> 1;
            int hf = tid & 1;
            const uint32_t* ka = reinterpret_cast<const uint32_t*>(g_qh + kg + 2 * u);
            const uint32_t* kb = ka + 4;
            uint32_t ua0 = ka[hf * 2], ua1 = ka[hf * 2 + 1];
            uint32_t ub0 = kb[hf * 2], ub1 = kb[hf * 2 + 1];
            sm.mma.sVT[buf][hf * 4 + 0][u] = __byte_perm(ua0, ub0, 0x5410);
            sm.mma.sVT[buf][hf * 4 + 1][u] = __byte_perm(ua0, ub0, 0x7632);
            sm.mma.sVT[buf][hf * 4 + 2][u] = __byte_perm(ua1, ub1, 0x5410);
            sm.mma.sVT[buf][hf * 4 + 3][u] = __byte_perm(ua1, ub1, 0x7632);
        }
    };

    load_chunk(0, 0);
    __syncthreads();

    for (int c = 0; c < 16; c++) {
        const int buf = c & 1;
        if (c < 15) load_chunk(c + 1, buf ^ 1);

        const uint32_t* k32 = reinterpret_cast<const uint32_t*>(sm.mma.sK[buf]);

#pragma unroll
        for (int t = 0; t < 8; t++) {
            uint32_t P00, P01, P10, P11;
            {
                int key = 16 * t + r;
                uint32_t kb0 = k32[key * 4 + m];
                uint32_t d0, d1;
                mma16808h(d0, d1, a0, a1, kb0);
                asm("ex2.approx.f16x2 %0, %1;" : "=r"(P00) : "r"(d0));
                asm("ex2.approx.f16x2 %0, %1;" : "=r"(P01) : "r"(d1));
                uint32_t w = sm.mma.sMaskP[buf][8 * t + m];
                P00 &= w;
                P01 &= w;
                float2 fa = __half22float2(*reinterpret_cast<half2*>(&P00));
                float2 fb = __half22float2(*reinterpret_cast<half2*>(&P01));
                l_lo += fa.x + fa.y;
                l_hi += fb.x + fb.y;
            }
            {
                int key = 16 * t + 8 + r;
                uint32_t kb0 = k32[key * 4 + m];
                uint32_t d0, d1;
                mma16808h(d0, d1, a0, a1, kb0);
                asm("ex2.approx.f16x2 %0, %1;" : "=r"(P10) : "r"(d0));
                asm("ex2.approx.f16x2 %0, %1;" : "=r"(P11) : "r"(d1));
                uint32_t w = sm.mma.sMaskP[buf][8 * t + 4 + m];
                P10 &= w;
                P11 &= w;
                float2 fa = __half22float2(*reinterpret_cast<half2*>(&P10));
                float2 fb = __half22float2(*reinterpret_cast<half2*>(&P11));
                l_lo += fa.x + fa.y;
                l_hi += fb.x + fb.y;
            }
            uint32_t vb0 = sm.mma.sVT[buf][r][t * 8 + m];
            uint32_t vb1 = sm.mma.sVT[buf][r][t * 8 + 4 + m];
            mma16816(O, P00, P01, P10, P11, vb0, vb1, O);
        }
        __syncthreads();
    }

    l_lo += __shfl_xor_sync(0xffffffffu, l_lo, 1);
    l_lo += __shfl_xor_sync(0xffffffffu, l_lo, 2);
    l_hi += __shfl_xor_sync(0xffffffffu, l_hi, 1);
    l_hi += __shfl_xor_sync(0xffffffffu, l_hi, 2);
    float inv_lo = 1.0f / l_lo;
    float inv_hi = 1.0f / l_hi;

    const int q0 = (qt << 7) + wid * 16 + r;
    uint32_t* op = g_attnh + ((size_t)b * SS + q0) * 128 + h * 4 + m;
    half2 o1 = __floats2half2_rn(O[0] * inv_lo, O[1] * inv_lo);
    half2 o2 = __floats2half2_rn(O[2] * inv_hi, O[3] * inv_hi);
    op[0]       = *reinterpret_cast<uint32_t*>(&o1);
    op[8 * 128] = *reinterpret_cast<uint32_t*>(&o2);
}

// ---------------------------------------------------------------------------
// Output projection via fp16 MMA (unchanged from R12).
// ---------------------------------------------------------------------------
__global__ __launch_bounds__(256, 2) void proj_kernel(
    const float* __restrict__ W,
    const float* __restrict__ bo,
    float*       __restrict__ Y)
{
    extern __shared__ uint32_t sh[];
    uint32_t* As = sh;
    uint32_t* Ws = sh + 64 * 132;

    const int tid = threadIdx.x;
    const int im0 = blockIdx.x * 64;
    const int jn0 = blockIdx.y * 64;

#pragma unroll
    for (int l = 0; l < 8; l++) {
        int idx = l * 256 + tid;
        int row = idx >> 5, c4 = idx & 31;
        uint4 v = *reinterpret_cast<const uint4*>(
            g_attnh + (size_t)(im0 + row) * 128 + c4 * 4);
        *reinterpret_cast<uint4*>(As + row * 132 + c4 * 4) = v;
    }
#pragma unroll
    for (int l = 0; l < 16; l++) {
        int idx = l * 256 + tid;
        int row = idx >> 6, c4 = idx & 63;
        float4 v = *reinterpret_cast<const float4*>(
            W + (size_t)(jn0 + row) * 256 + c4 * 4);
        half2 h0 = __floats2half2_rn(v.x, v.y);
        half2 h1 = __floats2half2_rn(v.z, v.w);
        uint2 pk = make_uint2(*reinterpret_cast<uint32_t*>(&h0),
                              *reinterpret_cast<uint32_t*>(&h1));
        *reinterpret_cast<uint2*>(Ws + row * 132 + c4 * 2) = pk;
    }
    __syncthreads();

    const int lane = tid & 31, wid = tid >> 5;
    const int r = lane >> 2, m = lane & 3;
    const int mb  = (wid & 3) * 16;
    const int nb0 = (wid >> 2) * 32;

    float acc[4][4];
#pragma unroll
    for (int nn = 0; nn < 4; nn++)
#pragma unroll
        for (int i = 0; i < 4; i++) acc[nn][i] = 0.f;

#pragma unroll
    for (int kc = 0; kc < 16; kc++) {
        uint32_t a0 = As[(mb + r) * 132 + kc * 8 + m];
        uint32_t a1 = As[(mb + r + 8) * 132 + kc * 8 + m];
        uint32_t a2 = As[(mb + r) * 132 + kc * 8 + 4 + m];
        uint32_t a3 = As[(mb + r + 8) * 132 + kc * 8 + 4 + m];
#pragma unroll
        for (int nn = 0; nn < 4; nn++) {
            uint32_t b0 = Ws[(nb0 + nn * 8 + r) * 132 + kc * 8 + m];
            uint32_t b1 = Ws[(nb0 + nn * 8 + r) * 132 + kc * 8 + 4 + m];
            mma16816(acc[nn], a0, a1, a2, a3, b0, b1, acc[nn]);
        }
    }

#pragma unroll
    for (int nn = 0; nn < 4; nn++) {
        int j = jn0 + nb0 + nn * 8 + 2 * m;
        float2 bv = *reinterpret_cast<const float2*>(bo + j);
        int i0 = im0 + mb + r;
        *reinterpret_cast<float2*>(Y + (size_t)i0 * 256 + j) =
            make_float2(acc[nn][0] + bv.x, acc[nn][1] + bv.y);
        *reinterpret_cast<float2*>(Y + (size_t)(i0 + 8) * 256 + j) =
            make_float2(acc[nn][2] + bv.x, acc[nn][3] + bv.y);
    }
}

// ---------------------------------------------------------------------------
extern "C" void kernel_launch(void* const* d_in, const int* in_sizes, int n_in,
                              void* d_out, int out_size)
{
    const float* x     = (const float*)d_in[0];
    const int*   mask  = (const int*)d_in[1];
    const float* theta = (const float*)d_in[2];
    const float* W     = (const float*)d_in[3];
    const float* bo    = (const float*)d_in[4];
    float*       out   = (float*)d_out;

    prep_kernel<<<512, 256>>>(x, theta);
    attn_kernel<<<64 * 16, 256>>>(mask);

    const int proj_smem = 2 * 64 * 132 * 4;   // 67.6 KB
    cudaFuncSetAttribute(proj_kernel,
                         cudaFuncAttributeMaxDynamicSharedMemorySize, proj_smem);
    dim3 grid(BB * SS / 64, EE / 64);  // (64, 4)
    proj_kernel<<<grid, 256, proj_smem>>>(W, bo, out);
}

// round 14
// speedup vs baseline: 1.2505x; 1.2505x over previous
#include <cuda_runtime.h>
#include <cuda_fp16.h>
#include <math.h>
#include <stdint.h>

#define BB 2
#define SS 2048
#define EE 256
#define HH 32

// log2(e)/sqrt(8): folded into the Q fragment.
#define CSCALE 0.51006972790221780093f

__device__ uint32_t g_attnh[BB * SS * EE / 2];  // attention output, fp16x2 [B,S,E]

// ---- MMA helpers (baseline PTX, compiles for compute_103) ----
__device__ __forceinline__ void mma16816(float d[4],
    uint32_t a0, uint32_t a1, uint32_t a2, uint32_t a3,
    uint32_t b0, uint32_t b1, const float c[4])
{
    asm volatile("mma.sync.aligned.m16n8k16.row.col.f32.f16.f16.f32 "
        "{%0,%1,%2,%3}, {%4,%5,%6,%7}, {%8,%9}, {%10,%11,%12,%13};"
        : "=f"(d[0]), "=f"(d[1]), "=f"(d[2]), "=f"(d[3])
        : "r"(a0), "r"(a1), "r"(a2), "r"(a3), "r"(b0), "r"(b1),
          "f"(c[0]), "f"(c[1]), "f"(c[2]), "f"(c[3]));
}
__device__ __forceinline__ void mma16808h(uint32_t& d0, uint32_t& d1,
    uint32_t a0, uint32_t a1, uint32_t b0)
{
    asm volatile("mma.sync.aligned.m16n8k8.row.col.f16.f16.f16.f16 "
        "{%0,%1}, {%2,%3}, {%4}, {%5,%6};"
        : "=r"(d0), "=r"(d1)
        : "r"(a0), "r"(a1), "r"(b0), "r"(0u), "r"(0u));
}

// cos(x+theta) for 8 dims -> packed fp16 uint4 (bit-identical to old prep).
__device__ __forceinline__ uint4 cos8_pack(const float* __restrict__ xr,
                                           const float* __restrict__ th)
{
    float4 v0 = *reinterpret_cast<const float4*>(xr);
    float4 v1 = *reinterpret_cast<const float4*>(xr + 4);
    half2 h0 = __floats2half2_rn(__cosf(v0.x + th[0]), __cosf(v0.y + th[1]));
    half2 h1 = __floats2half2_rn(__cosf(v0.z + th[2]), __cosf(v0.w + th[3]));
    half2 h2 = __floats2half2_rn(__cosf(v1.x + th[4]), __cosf(v1.y + th[5]));
    half2 h3 = __floats2half2_rn(__cosf(v1.z + th[6]), __cosf(v1.w + th[7]));
    return make_uint4(*reinterpret_cast<uint32_t*>(&h0),
                      *reinterpret_cast<uint32_t*>(&h1),
                      *reinterpret_cast<uint32_t*>(&h2),
                      *reinterpret_cast<uint32_t*>(&h3));
}

// ---------------------------------------------------------------------------
// Fused flash attention: cos(x+theta)->fp16 computed in the tile loaders
// (MUFU/FMA pipes, idle under the tensor-bound main loop). R12 MMA core.
// ---------------------------------------------------------------------------
__global__ __launch_bounds__(256, 4) void attn_kernel(
    const float* __restrict__ x,
    const int*   __restrict__ mask,
    const float* __restrict__ theta)
{
    __shared__ uint4    sK[2][128];      // K tile, 16B (8 fp16) per key
    __shared__ uint32_t sMaskP[2][64];   // packed mask halves per key pair
    __shared__ uint32_t sVT[2][8][68];   // V^T [dim][key-pair fp16x2], padded
    __shared__ uint4    sQ[128];         // Q tile (fp16, this CTA's queries)
    __shared__ float    sTh[8];

    const int tid  = threadIdx.x;
    const int wid  = tid >> 5;
    const int lane = tid & 31;
    const int r = lane >> 2;             // fragment row group
    const int m = lane & 3;              // fragment k group
    const int bh = blockIdx.x >> 4;
    const int qt = blockIdx.x & 15;
    const int b  = bh >> 5;
    const int h  = bh & 31;

    if (tid < 8) sTh[tid] = theta[tid];
    __syncthreads();

    const float* xh = x + (size_t)b * SS * EE + h * 8;   // + s*EE indexes token

    // --- Tile loader: compute K fp16 from x, build V^T via pair-shfl ---
    auto load_chunk = [&](int c, int buf) {
        const int kglob = c << 7;
        if (tid < 128) {
            uint4 H = cos8_pack(xh + (size_t)(kglob + tid) * EE, sTh);
            sK[buf][tid] = H;
            // pair exchange: token 2u <-> 2u+1 (adjacent lanes)
            uint4 G;
            G.x = __shfl_xor_sync(0xffffffffu, H.x, 1);
            G.y = __shfl_xor_sync(0xffffffffu, H.y, 1);
            G.z = __shfl_xor_sync(0xffffffffu, H.z, 1);
            G.w = __shfl_xor_sync(0xffffffffu, H.w, 1);
            const int u  = tid >> 1;
            const int hf = tid & 1;
            uint32_t A[4] = {H.x, H.y, H.z, H.w};   // will hold even token
            uint32_t Bv[4] = {G.x, G.y, G.z, G.w};  // will hold odd token
            if (hf) {                                // odd lane: swap roles
                A[0] = G.x; A[1] = G.y; A[2] = G.z; A[3] = G.w;
                Bv[0] = H.x; Bv[1] = H.y; Bv[2] = H.z; Bv[3] = H.w;
            }
            uint32_t ua0 = A[hf * 2], ua1 = A[hf * 2 + 1];
            uint32_t ub0 = Bv[hf * 2], ub1 = Bv[hf * 2 + 1];
            sVT[buf][hf * 4 + 0][u] = __byte_perm(ua0, ub0, 0x5410);
            sVT[buf][hf * 4 + 1][u] = __byte_perm(ua0, ub0, 0x7632);
            sVT[buf][hf * 4 + 2][u] = __byte_perm(ua1, ub1, 0x5410);
            sVT[buf][hf * 4 + 3][u] = __byte_perm(ua1, ub1, 0x7632);
        } else if (tid < 192) {
            int u = tid - 128;
            int2 mm = *reinterpret_cast<const int2*>(
                mask + b * SS + (c << 7) + 2 * u);
            sMaskP[buf][u] = (mm.x ? 0x0000FFFFu : 0u) |
                             (mm.y ? 0xFFFF0000u : 0u);
        }
    };

    // --- Prologue: Q tile + chunk 0 ---
    if (tid < 128)
        sQ[tid] = cos8_pack(xh + (size_t)((qt << 7) + tid) * EE, sTh);
    load_chunk(0, 0);
    __syncthreads();

    // --- Fixed A fragment: this warp's 16 queries, pre-scaled by CSCALE ---
    const uint32_t* qw = reinterpret_cast<const uint32_t*>(sQ + wid * 16);
    uint32_t a0r = qw[r * 4 + m];                // row r,   dims 2m,2m+1
    uint32_t a1r = qw[(r + 8) * 4 + m];          // row r+8
    float2 f0 = __half22float2(*reinterpret_cast<half2*>(&a0r));
    float2 f1 = __half22float2(*reinterpret_cast<half2*>(&a1r));
    half2 s0 = __floats2half2_rn(f0.x * CSCALE, f0.y * CSCALE);
    half2 s1 = __floats2half2_rn(f1.x * CSCALE, f1.y * CSCALE);
    const uint32_t a0 = *reinterpret_cast<uint32_t*>(&s0);
    const uint32_t a1 = *reinterpret_cast<uint32_t*>(&s1);

    float O[4] = {0.f, 0.f, 0.f, 0.f};   // output fragment [16q x 8d]
    float l_lo = 0.f, l_hi = 0.f;        // softmax denominators (rows r, r+8)

    for (int c = 0; c < 16; c++) {
        const int buf = c & 1;
        if (c < 15) load_chunk(c + 1, buf ^ 1);

        const uint32_t* k32 = reinterpret_cast<const uint32_t*>(sK[buf]);

        // --- Interleaved: S (fp16-acc k8 MMA) -> exp2 -> mask AND -> PV ---
#pragma unroll
        for (int t = 0; t < 8; t++) {
            uint32_t P00, P01, P10, P11;
            {
                int key = 16 * t + r;                  // j = 2t
                uint32_t kb0 = k32[key * 4 + m];
                uint32_t d0, d1;
                mma16808h(d0, d1, a0, a1, kb0);
                asm("ex2.approx.f16x2 %0, %1;" : "=r"(P00) : "r"(d0));
                asm("ex2.approx.f16x2 %0, %1;" : "=r"(P01) : "r"(d1));
                uint32_t w = sMaskP[buf][8 * t + m];
                P00 &= w;
                P01 &= w;
                float2 fa = __half22float2(*reinterpret_cast<half2*>(&P00));
                float2 fb = __half22float2(*reinterpret_cast<half2*>(&P01));
                l_lo += fa.x + fa.y;
                l_hi += fb.x + fb.y;
            }
            {
                int key = 16 * t + 8 + r;              // j = 2t+1
                uint32_t kb0 = k32[key * 4 + m];
                uint32_t d0, d1;
                mma16808h(d0, d1, a0, a1, kb0);
                asm("ex2.approx.f16x2 %0, %1;" : "=r"(P10) : "r"(d0));
                asm("ex2.approx.f16x2 %0, %1;" : "=r"(P11) : "r"(d1));
                uint32_t w = sMaskP[buf][8 * t + 4 + m];
                P10 &= w;
                P11 &= w;
                float2 fa = __half22float2(*reinterpret_cast<half2*>(&P10));
                float2 fb = __half22float2(*reinterpret_cast<half2*>(&P11));
                l_lo += fa.x + fa.y;
                l_hi += fb.x + fb.y;
            }
            uint32_t vb0 = sVT[buf][r][t * 8 + m];
            uint32_t vb1 = sVT[buf][r][t * 8 + 4 + m];
            mma16816(O, P00, P01, P10, P11, vb0, vb1, O);
        }
        __syncthreads();
    }

    // --- Reduce denominators across the 4 threads sharing each row ---
    l_lo += __shfl_xor_sync(0xffffffffu, l_lo, 1);
    l_lo += __shfl_xor_sync(0xffffffffu, l_lo, 2);
    l_hi += __shfl_xor_sync(0xffffffffu, l_hi, 1);
    l_hi += __shfl_xor_sync(0xffffffffu, l_hi, 2);
    float inv_lo = 1.0f / l_lo;
    float inv_hi = 1.0f / l_hi;

    const int q0 = (qt << 7) + wid * 16 + r;
    uint32_t* op = g_attnh + ((size_t)b * SS + q0) * 128 + h * 4 + m;
    half2 o1 = __floats2half2_rn(O[0] * inv_lo, O[1] * inv_lo);
    half2 o2 = __floats2half2_rn(O[2] * inv_hi, O[3] * inv_hi);
    op[0]       = *reinterpret_cast<uint32_t*>(&o1);
    op[8 * 128] = *reinterpret_cast<uint32_t*>(&o2);
}

// ---------------------------------------------------------------------------
// Output projection via fp16 MMA: Y[4096,256] = A @ W^T + b (R12, unchanged).
// ---------------------------------------------------------------------------
__global__ __launch_bounds__(256, 2) void proj_kernel(
    const float* __restrict__ W,
    const float* __restrict__ bo,
    float*       __restrict__ Y)
{
    extern __shared__ uint32_t sh[];     // As: 64*132 u32, Ws: 64*132 u32
    uint32_t* As = sh;
    uint32_t* Ws = sh + 64 * 132;

    const int tid = threadIdx.x;
    const int im0 = blockIdx.x * 64;
    const int jn0 = blockIdx.y * 64;

#pragma unroll
    for (int l = 0; l < 8; l++) {
        int idx = l * 256 + tid;
        int row = idx >> 5, c4 = idx & 31;
        uint4 v = *reinterpret_cast<const uint4*>(
            g_attnh + (size_t)(im0 + row) * 128 + c4 * 4);
        *reinterpret_cast<uint4*>(As + row * 132 + c4 * 4) = v;
    }
#pragma unroll
    for (int l = 0; l < 16; l++) {
        int idx = l * 256 + tid;
        int row = idx >> 6, c4 = idx & 63;
        float4 v = *reinterpret_cast<const float4*>(
            W + (size_t)(jn0 + row) * 256 + c4 * 4);
        half2 h0 = __floats2half2_rn(v.x, v.y);
        half2 h1 = __floats2half2_rn(v.z, v.w);
        uint2 pk = make_uint2(*reinterpret_cast<uint32_t*>(&h0),
                              *reinterpret_cast<uint32_t*>(&h1));
        *reinterpret_cast<uint2*>(Ws + row * 132 + c4 * 2) = pk;
    }
    __syncthreads();

    const int lane = tid & 31, wid = tid >> 5;
    const int r = lane >> 2, m = lane & 3;
    const int mb  = (wid & 3) * 16;
    const int nb0 = (wid >> 2) * 32;

    float acc[4][4];
#pragma unroll
    for (int nn = 0; nn < 4; nn++)
#pragma unroll
        for (int i = 0; i < 4; i++) acc[nn][i] = 0.f;

#pragma unroll
    for (int kc = 0; kc < 16; kc++) {
        uint32_t a0 = As[(mb + r) * 132 + kc * 8 + m];
        uint32_t a1 = As[(mb + r + 8) * 132 + kc * 8 + m];
        uint32_t a2 = As[(mb + r) * 132 + kc * 8 + 4 + m];
        uint32_t a3 = As[(mb + r + 8) * 132 + kc * 8 + 4 + m];
#pragma unroll
        for (int nn = 0; nn < 4; nn++) {
            uint32_t b0 = Ws[(nb0 + nn * 8 + r) * 132 + kc * 8 + m];
            uint32_t b1 = Ws[(nb0 + nn * 8 + r) * 132 + kc * 8 + 4 + m];
            mma16816(acc[nn], a0, a1, a2, a3, b0, b1, acc[nn]);
        }
    }

#pragma unroll
    for (int nn = 0; nn < 4; nn++) {
        int j = jn0 + nb0 + nn * 8 + 2 * m;
        float2 bv = *reinterpret_cast<const float2*>(bo + j);
        int i0 = im0 + mb + r;
        *reinterpret_cast<float2*>(Y + (size_t)i0 * 256 + j) =
            make_float2(acc[nn][0] + bv.x, acc[nn][1] + bv.y);
        *reinterpret_cast<float2*>(Y + (size_t)(i0 + 8) * 256 + j) =
            make_float2(acc[nn][2] + bv.x, acc[nn][3] + bv.y);
    }
}

// ---------------------------------------------------------------------------
extern "C" void kernel_launch(void* const* d_in, const int* in_sizes, int n_in,
                              void* d_out, int out_size)
{
    const float* x     = (const float*)d_in[0];
    const int*   mask  = (const int*)d_in[1];
    const float* theta = (const float*)d_in[2];
    const float* W     = (const float*)d_in[3];
    const float* bo    = (const float*)d_in[4];
    float*       out   = (float*)d_out;

    attn_kernel<<<64 * 16, 256>>>(x, mask, theta);

    const int proj_smem = 2 * 64 * 132 * 4;   // 67.6 KB
    cudaFuncSetAttribute(proj_kernel,
                         cudaFuncAttributeMaxDynamicSharedMemorySize, proj_smem);
    dim3 grid(BB * SS / 64, EE / 64);  // (64, 4)
    proj_kernel<<<grid, 256, proj_smem>>>(W, bo, out);
}

// round 15
// speedup vs baseline: 1.4033x; 1.1222x over previous
#include <cuda_runtime.h>
#include <cuda_fp16.h>
#include <math.h>
#include <stdint.h>

#define BB 2
#define SS 2048
#define EE 256
#define HH 32

// log2(e)/sqrt(8): folded into the Q fragment.
#define CSCALE 0.51006972790221780093f

__device__ uint32_t g_attnh[BB * SS * EE / 2];  // attention output, fp16x2 [B,S,E]
__device__ uint4 g_qh[64 * 2048];               // fp16 cos(x+theta): 8 vals (16B) per (bh,s)

// Warp-level fp16 MMA m16n8k16, D/C fp32. Baseline sm_80 PTX.
__device__ __forceinline__ void mma16816(float d[4],
    uint32_t a0, uint32_t a1, uint32_t a2, uint32_t a3,
    uint32_t b0, uint32_t b1, const float c[4])
{
    asm volatile("mma.sync.aligned.m16n8k16.row.col.f32.f16.f16.f32 "
        "{%0,%1,%2,%3}, {%4,%5,%6,%7}, {%8,%9}, {%10,%11,%12,%13};"
        : "=f"(d[0]), "=f"(d[1]), "=f"(d[2]), "=f"(d[3])
        : "r"(a0), "r"(a1), "r"(a2), "r"(a3), "r"(b0), "r"(b1),
          "f"(c[0]), "f"(c[1]), "f"(c[2]), "f"(c[3]));
}
// Warp-level fp16 MMA m16n8k8 with FP16 accumulator: D packed f16x2.
__device__ __forceinline__ void mma16808h(uint32_t& d0, uint32_t& d1,
    uint32_t a0, uint32_t a1, uint32_t b0)
{
    asm volatile("mma.sync.aligned.m16n8k8.row.col.f16.f16.f16.f16 "
        "{%0,%1}, {%2,%3}, {%4}, {%5,%6};"
        : "=r"(d0), "=r"(d1)
        : "r"(a0), "r"(a1), "r"(b0), "r"(0u), "r"(0u));
}

// ---------------------------------------------------------------------------
// Prep: q = cos(x + theta) -> fp16 via smem transpose.
// Block = (b, 4 tokens): 1 float4 load + 1 uint2 store per thread. 1024 blocks.
// ---------------------------------------------------------------------------
__global__ __launch_bounds__(256) void prep_kernel(
    const float* __restrict__ x,
    const float* __restrict__ theta)
{
    __shared__ uint2 tile[32][9];        // [h][s_local*2 + hf]

    const int t   = threadIdx.x;
    const int blk = blockIdx.x;          // 0..1023
    const int b   = blk >> 9;
    const int s0  = (blk & 511) << 2;    // 4 tokens
    float th[8];
#pragma unroll
    for (int d = 0; d < 8; d++) th[d] = __ldg(theta + d);

    const float* xb = x + ((size_t)b * SS + s0) * EE;
    {
        int row = t >> 6;                // token 0..3
        int c4  = t & 63;                // float4 within row
        float4 v = *reinterpret_cast<const float4*>(xb + (size_t)row * EE + c4 * 4);
        int hf = c4 & 1;
        int db = hf * 4;
        half2 h0 = __floats2half2_rn(__cosf(v.x + th[db + 0]), __cosf(v.y + th[db + 1]));
        half2 h1 = __floats2half2_rn(__cosf(v.z + th[db + 2]), __cosf(v.w + th[db + 3]));
        tile[c4 >> 1][row * 2 + hf] =
            make_uint2(*reinterpret_cast<uint32_t*>(&h0),
                       *reinterpret_cast<uint32_t*>(&h1));
    }
    __syncthreads();
    {
        int h  = t >> 3;                 // head
        int in = t & 7;                  // s_local*2 + hf
        uint2 v = tile[h][in];
        uint2* dst = reinterpret_cast<uint2*>(g_qh + (((b << 5) + h) << 11) + s0);
        dst[in] = v;
    }
}

// ---------------------------------------------------------------------------
// Warp-MMA flash attention (R12, unchanged — proven 52.6us tensor floor).
// ---------------------------------------------------------------------------
__global__ __launch_bounds__(256, 4) void attn_kernel(const int* __restrict__ mask)
{
    __shared__ uint4    sK[2][128];      // K tile, 16B (8 fp16) per key
    __shared__ uint32_t sMaskP[2][64];   // packed mask halves per key pair
    __shared__ uint32_t sVT[2][8][68];   // V^T [dim][key-pair fp16x2], padded

    const int tid  = threadIdx.x;
    const int wid  = tid >> 5;
    const int lane = tid & 31;
    const int r = lane >> 2;             // fragment row group
    const int m = lane & 3;              // fragment k group
    const int bh = blockIdx.x >> 4;
    const int qt = blockIdx.x & 15;
    const int b  = bh >> 5;

    // --- Fixed A fragment: this warp's 16 queries, pre-scaled by CSCALE ---
    const int qbase = (bh << 11) + (qt << 7) + wid * 16;
    const uint32_t* qw = reinterpret_cast<const uint32_t*>(g_qh + qbase);
    uint32_t a0r = qw[r * 4 + m];                // row r,   dims 2m,2m+1
    uint32_t a1r = qw[(r + 8) * 4 + m];          // row r+8
    float2 f0 = __half22float2(*reinterpret_cast<half2*>(&a0r));
    float2 f1 = __half22float2(*reinterpret_cast<half2*>(&a1r));
    half2 s0 = __floats2half2_rn(f0.x * CSCALE, f0.y * CSCALE);
    half2 s1 = __floats2half2_rn(f1.x * CSCALE, f1.y * CSCALE);
    const uint32_t a0 = *reinterpret_cast<uint32_t*>(&s0);
    const uint32_t a1 = *reinterpret_cast<uint32_t*>(&s1);

    float O[4] = {0.f, 0.f, 0.f, 0.f};   // output fragment [16q x 8d]
    float l_lo = 0.f, l_hi = 0.f;        // softmax denominators (rows r, r+8)

    auto load_chunk = [&](int c, int buf) {
        const int kg = (bh << 11) + (c << 7);
        if (tid < 128) {
            sK[buf][tid] = g_qh[kg + tid];
            if (tid < 64) {
                int2 mm = *reinterpret_cast<const int2*>(
                    mask + b * SS + (c << 7) + 2 * tid);
                sMaskP[buf][tid] = (mm.x ? 0x0000FFFFu : 0u) |
                                   (mm.y ? 0xFFFF0000u : 0u);
            }
        } else {
            int u  = (tid - 128) >> 1;             // key pair
            int hf = tid & 1;                      // dim half (4 dims)
            const uint32_t* ka = reinterpret_cast<const uint32_t*>(g_qh + kg + 2 * u);
            const uint32_t* kb = ka + 4;
            uint32_t ua0 = ka[hf * 2], ua1 = ka[hf * 2 + 1];
            uint32_t ub0 = kb[hf * 2], ub1 = kb[hf * 2 + 1];
            sVT[buf][hf * 4 + 0][u] = __byte_perm(ua0, ub0, 0x5410);
            sVT[buf][hf * 4 + 1][u] = __byte_perm(ua0, ub0, 0x7632);
            sVT[buf][hf * 4 + 2][u] = __byte_perm(ua1, ub1, 0x5410);
            sVT[buf][hf * 4 + 3][u] = __byte_perm(ua1, ub1, 0x7632);
        }
    };

    load_chunk(0, 0);
    __syncthreads();

    for (int c = 0; c < 16; c++) {
        const int buf = c & 1;
        if (c < 15) load_chunk(c + 1, buf ^ 1);

        const uint32_t* k32 = reinterpret_cast<const uint32_t*>(sK[buf]);

#pragma unroll
        for (int t = 0; t < 8; t++) {
            uint32_t P00, P01, P10, P11;
            {
                int key = 16 * t + r;                  // j = 2t
                uint32_t kb0 = k32[key * 4 + m];
                uint32_t d0, d1;
                mma16808h(d0, d1, a0, a1, kb0);
                asm("ex2.approx.f16x2 %0, %1;" : "=r"(P00) : "r"(d0));
                asm("ex2.approx.f16x2 %0, %1;" : "=r"(P01) : "r"(d1));
                uint32_t w = sMaskP[buf][8 * t + m];
                P00 &= w;
                P01 &= w;
                float2 fa = __half22float2(*reinterpret_cast<half2*>(&P00));
                float2 fb = __half22float2(*reinterpret_cast<half2*>(&P01));
                l_lo += fa.x + fa.y;
                l_hi += fb.x + fb.y;
            }
            {
                int key = 16 * t + 8 + r;              // j = 2t+1
                uint32_t kb0 = k32[key * 4 + m];
                uint32_t d0, d1;
                mma16808h(d0, d1, a0, a1, kb0);
                asm("ex2.approx.f16x2 %0, %1;" : "=r"(P10) : "r"(d0));
                asm("ex2.approx.f16x2 %0, %1;" : "=r"(P11) : "r"(d1));
                uint32_t w = sMaskP[buf][8 * t + 4 + m];
                P10 &= w;
                P11 &= w;
                float2 fa = __half22float2(*reinterpret_cast<half2*>(&P10));
                float2 fb = __half22float2(*reinterpret_cast<half2*>(&P11));
                l_lo += fa.x + fa.y;
                l_hi += fb.x + fb.y;
            }
            uint32_t vb0 = sVT[buf][r][t * 8 + m];
            uint32_t vb1 = sVT[buf][r][t * 8 + 4 + m];
            mma16816(O, P00, P01, P10, P11, vb0, vb1, O);
        }
        __syncthreads();
    }

    l_lo += __shfl_xor_sync(0xffffffffu, l_lo, 1);
    l_lo += __shfl_xor_sync(0xffffffffu, l_lo, 2);
    l_hi += __shfl_xor_sync(0xffffffffu, l_hi, 1);
    l_hi += __shfl_xor_sync(0xffffffffu, l_hi, 2);
    float inv_lo = 1.0f / l_lo;
    float inv_hi = 1.0f / l_hi;

    const int h  = bh & 31;
    const int q0 = (qt << 7) + wid * 16 + r;
    uint32_t* op = g_attnh + ((size_t)b * SS + q0) * 128 + h * 4 + m;
    half2 o1 = __floats2half2_rn(O[0] * inv_lo, O[1] * inv_lo);
    half2 o2 = __floats2half2_rn(O[2] * inv_hi, O[3] * inv_hi);
    op[0]       = *reinterpret_cast<uint32_t*>(&o1);
    op[8 * 128] = *reinterpret_cast<uint32_t*>(&o2);
}

// ---------------------------------------------------------------------------
// Output projection via fp16 MMA: Y[4096,256] = A @ W^T + b.
// Retiled 64x32 (smem 50.7KB -> occ 4, grid 512) for latency hiding.
// ---------------------------------------------------------------------------
__global__ __launch_bounds__(256, 4) void proj_kernel(
    const float* __restrict__ W,
    const float* __restrict__ bo,
    float*       __restrict__ Y)
{
    extern __shared__ uint32_t sh[];     // As: 64*132 u32, Ws: 32*132 u32
    uint32_t* As = sh;
    uint32_t* Ws = sh + 64 * 132;

    const int tid = threadIdx.x;
    const int im0 = blockIdx.x * 64;
    const int jn0 = blockIdx.y * 32;

    // Stage A (already fp16): 64 rows x 128 u32, uint4 loads
#pragma unroll
    for (int l = 0; l < 8; l++) {
        int idx = l * 256 + tid;
        int row = idx >> 5, c4 = idx & 31;
        uint4 v = *reinterpret_cast<const uint4*>(
            g_attnh + (size_t)(im0 + row) * 128 + c4 * 4);
        *reinterpret_cast<uint4*>(As + row * 132 + c4 * 4) = v;
    }
    // Stage W with fp32->fp16 conversion: 32 rows x 64 float4
#pragma unroll
    for (int l = 0; l < 8; l++) {
        int idx = l * 256 + tid;
        int row = idx >> 6, c4 = idx & 63;
        float4 v = *reinterpret_cast<const float4*>(
            W + (size_t)(jn0 + row) * 256 + c4 * 4);
        half2 h0 = __floats2half2_rn(v.x, v.y);
        half2 h1 = __floats2half2_rn(v.z, v.w);
        uint2 pk = make_uint2(*reinterpret_cast<uint32_t*>(&h0),
                              *reinterpret_cast<uint32_t*>(&h1));
        *reinterpret_cast<uint2*>(Ws + row * 132 + c4 * 2) = pk;
    }
    __syncthreads();

    const int lane = tid & 31, wid = tid >> 5;
    const int r = lane >> 2, m = lane & 3;
    const int mb  = (wid & 3) * 16;      // m-block
    const int nb0 = (wid >> 2) * 16;     // 2 n8-blocks

    float acc[2][4];
#pragma unroll
    for (int nn = 0; nn < 2; nn++)
#pragma unroll
        for (int i = 0; i < 4; i++) acc[nn][i] = 0.f;

#pragma unroll
    for (int kc = 0; kc < 16; kc++) {
        uint32_t a0 = As[(mb + r) * 132 + kc * 8 + m];
        uint32_t a1 = As[(mb + r + 8) * 132 + kc * 8 + m];
        uint32_t a2 = As[(mb + r) * 132 + kc * 8 + 4 + m];
        uint32_t a3 = As[(mb + r + 8) * 132 + kc * 8 + 4 + m];
#pragma unroll
        for (int nn = 0; nn < 2; nn++) {
            uint32_t b0 = Ws[(nb0 + nn * 8 + r) * 132 + kc * 8 + m];
            uint32_t b1 = Ws[(nb0 + nn * 8 + r) * 132 + kc * 8 + 4 + m];
            mma16816(acc[nn], a0, a1, a2, a3, b0, b1, acc[nn]);
        }
    }

    // Epilogue: bias + fp32 stores
#pragma unroll
    for (int nn = 0; nn < 2; nn++) {
        int j = jn0 + nb0 + nn * 8 + 2 * m;
        float2 bv = *reinterpret_cast<const float2*>(bo + j);
        int i0 = im0 + mb + r;
        *reinterpret_cast<float2*>(Y + (size_t)i0 * 256 + j) =
            make_float2(acc[nn][0] + bv.x, acc[nn][1] + bv.y);
        *reinterpret_cast<float2*>(Y + (size_t)(i0 + 8) * 256 + j) =
            make_float2(acc[nn][2] + bv.x, acc[nn][3] + bv.y);
    }
}

// ---------------------------------------------------------------------------
extern "C" void kernel_launch(void* const* d_in, const int* in_sizes, int n_in,
                              void* d_out, int out_size)
{
    const float* x     = (const float*)d_in[0];
    const int*   mask  = (const int*)d_in[1];
    const float* theta = (const float*)d_in[2];
    const float* W     = (const float*)d_in[3];
    const float* bo    = (const float*)d_in[4];
    float*       out   = (float*)d_out;

    prep_kernel<<<1024, 256>>>(x, theta);
    attn_kernel<<<64 * 16, 256>>>(mask);

    const int proj_smem = (64 + 32) * 132 * 4;   // 50.7 KB
    cudaFuncSetAttribute(proj_kernel,
                         cudaFuncAttributeMaxDynamicSharedMemorySize, proj_smem);
    dim3 grid(BB * SS / 64, EE / 32);  // (64, 8)
    proj_kernel<<<grid, 256, proj_smem>>>(W, bo, out);
}

// round 16
// speedup vs baseline: 1.4482x; 1.0320x over previous
#include <cuda_runtime.h>
#include <cuda_fp16.h>
#include <math.h>
#include <stdint.h>

#define BB 2
#define SS 2048
#define EE 256
#define HH 32

// log2(e)/sqrt(8): folded into the Q fragment.
#define CSCALE 0.51006972790221780093f

__device__ uint32_t g_attnh[BB * SS * EE / 2];  // attention output, fp16x2 [B,S,E]
__device__ uint4 g_qh[64 * 2048];               // fp16 cos(x+theta): 8 vals (16B) per (bh,s)
__device__ uint32_t g_wh[EE * EE / 2];          // W pre-converted to fp16x2

// Warp-level fp16 MMA m16n8k16, D/C fp32. Baseline sm_80 PTX.
__device__ __forceinline__ void mma16816(float d[4],
    uint32_t a0, uint32_t a1, uint32_t a2, uint32_t a3,
    uint32_t b0, uint32_t b1, const float c[4])
{
    asm volatile("mma.sync.aligned.m16n8k16.row.col.f32.f16.f16.f32 "
        "{%0,%1,%2,%3}, {%4,%5,%6,%7}, {%8,%9}, {%10,%11,%12,%13};"
        : "=f"(d[0]), "=f"(d[1]), "=f"(d[2]), "=f"(d[3])
        : "r"(a0), "r"(a1), "r"(a2), "r"(a3), "r"(b0), "r"(b1),
          "f"(c[0]), "f"(c[1]), "f"(c[2]), "f"(c[3]));
}
// Warp-level fp16 MMA m16n8k8 with FP16 accumulator: D packed f16x2.
__device__ __forceinline__ void mma16808h(uint32_t& d0, uint32_t& d1,
    uint32_t a0, uint32_t a1, uint32_t b0)
{
    asm volatile("mma.sync.aligned.m16n8k8.row.col.f16.f16.f16.f16 "
        "{%0,%1}, {%2,%3}, {%4}, {%5,%6};"
        : "=r"(d0), "=r"(d1)
        : "r"(a0), "r"(a1), "r"(b0), "r"(0u), "r"(0u));
}

// ---------------------------------------------------------------------------
// Prep: blocks 0..511  -> q = cos(x+theta) fp16 via smem transpose (R12).
//       blocks 512..543 -> W fp32 -> fp16 (for the proj kernel).
// ---------------------------------------------------------------------------
__global__ __launch_bounds__(256) void prep_kernel(
    const float* __restrict__ x,
    const float* __restrict__ theta,
    const float* __restrict__ W)
{
    const int t   = threadIdx.x;
    const int blk = blockIdx.x;

    if (blk >= 512) {
        // --- W conversion: 32 blocks x 512 float4 ---
        int base = (blk - 512) * 512 + (t & 255) * 2 + ((t >> 8));
#pragma unroll
        for (int l = 0; l < 2; l++) {
            int i4 = (blk - 512) * 512 + l * 256 + t;   // float4 index
            float4 v = *reinterpret_cast<const float4*>(W + i4 * 4);
            half2 h0 = __floats2half2_rn(v.x, v.y);
            half2 h1 = __floats2half2_rn(v.z, v.w);
            uint2 pk = make_uint2(*reinterpret_cast<uint32_t*>(&h0),
                                  *reinterpret_cast<uint32_t*>(&h1));
            *reinterpret_cast<uint2*>(g_wh + i4 * 2) = pk;
        }
        (void)base;
        return;
    }

    __shared__ uint2 tile[32][18];       // [h][s_local*2 + hf]
    const int b   = blk >> 8;
    const int s0  = (blk & 255) << 3;    // 8 tokens
    float th[8];
#pragma unroll
    for (int d = 0; d < 8; d++) th[d] = __ldg(theta + d);

    const float* xb = x + ((size_t)b * SS + s0) * EE;
#pragma unroll
    for (int l = 0; l < 2; l++) {
        int idx = t + l * 256;
        int row = idx >> 6;
        int c4  = idx & 63;
        float4 v = *reinterpret_cast<const float4*>(xb + (size_t)row * EE + c4 * 4);
        int hf = c4 & 1;
        int db = hf * 4;
        half2 h0 = __floats2half2_rn(__cosf(v.x + th[db + 0]), __cosf(v.y + th[db + 1]));
        half2 h1 = __floats2half2_rn(__cosf(v.z + th[db + 2]), __cosf(v.w + th[db + 3]));
        tile[c4 >> 1][row * 2 + hf] =
            make_uint2(*reinterpret_cast<uint32_t*>(&h0),
                       *reinterpret_cast<uint32_t*>(&h1));
    }
    __syncthreads();
#pragma unroll
    for (int l = 0; l < 2; l++) {
        int idx = t + l * 256;
        int h  = idx >> 4;
        int in = idx & 15;
        uint2 v = tile[h][in];
        uint2* dst = reinterpret_cast<uint2*>(g_qh + (((b << 5) + h) << 11) + s0);
        dst[in] = v;
    }
}

// ---------------------------------------------------------------------------
// Warp-MMA flash attention (R12, byte-identical — proven 50.4us floor).
// ---------------------------------------------------------------------------
__global__ __launch_bounds__(256, 4) void attn_kernel(const int* __restrict__ mask)
{
    __shared__ uint4    sK[2][128];
    __shared__ uint32_t sMaskP[2][64];
    __shared__ uint32_t sVT[2][8][68];

    const int tid  = threadIdx.x;
    const int wid  = tid >> 5;
    const int lane = tid & 31;
    const int r = lane >> 2;
    const int m = lane & 3;
    const int bh = blockIdx.x >> 4;
    const int qt = blockIdx.x & 15;
    const int b  = bh >> 5;

    const int qbase = (bh << 11) + (qt << 7) + wid * 16;
    const uint32_t* qw = reinterpret_cast<const uint32_t*>(g_qh + qbase);
    uint32_t a0r = qw[r * 4 + m];
    uint32_t a1r = qw[(r + 8) * 4 + m];
    float2 f0 = __half22float2(*reinterpret_cast<half2*>(&a0r));
    float2 f1 = __half22float2(*reinterpret_cast<half2*>(&a1r));
    half2 s0 = __floats2half2_rn(f0.x * CSCALE, f0.y * CSCALE);
    half2 s1 = __floats2half2_rn(f1.x * CSCALE, f1.y * CSCALE);
    const uint32_t a0 = *reinterpret_cast<uint32_t*>(&s0);
    const uint32_t a1 = *reinterpret_cast<uint32_t*>(&s1);

    float O[4] = {0.f, 0.f, 0.f, 0.f};
    float l_lo = 0.f, l_hi = 0.f;

    auto load_chunk = [&](int c, int buf) {
        const int kg = (bh << 11) + (c << 7);
        if (tid < 128) {
            sK[buf][tid] = g_qh[kg + tid];
            if (tid < 64) {
                int2 mm = *reinterpret_cast<const int2*>(
                    mask + b * SS + (c << 7) + 2 * tid);
                sMaskP[buf][tid] = (mm.x ? 0x0000FFFFu : 0u) |
                                   (mm.y ? 0xFFFF0000u : 0u);
            }
        } else {
            int u  = (tid - 128) >> 1;
            int hf = tid & 1;
            const uint32_t* ka = reinterpret_cast<const uint32_t*>(g_qh + kg + 2 * u);
            const uint32_t* kb = ka + 4;
            uint32_t ua0 = ka[hf * 2], ua1 = ka[hf * 2 + 1];
            uint32_t ub0 = kb[hf * 2], ub1 = kb[hf * 2 + 1];
            sVT[buf][hf * 4 + 0][u] = __byte_perm(ua0, ub0, 0x5410);
            sVT[buf][hf * 4 + 1][u] = __byte_perm(ua0, ub0, 0x7632);
            sVT[buf][hf * 4 + 2][u] = __byte_perm(ua1, ub1, 0x5410);
            sVT[buf][hf * 4 + 3][u] = __byte_perm(ua1, ub1, 0x7632);
        }
    };

    load_chunk(0, 0);
    __syncthreads();

    for (int c = 0; c < 16; c++) {
        const int buf = c & 1;
        if (c < 15) load_chunk(c + 1, buf ^ 1);

        const uint32_t* k32 = reinterpret_cast<const uint32_t*>(sK[buf]);

#pragma unroll
        for (int t = 0; t < 8; t++) {
            uint32_t P00, P01, P10, P11;
            {
                int key = 16 * t + r;
                uint32_t kb0 = k32[key * 4 + m];
                uint32_t d0, d1;
                mma16808h(d0, d1, a0, a1, kb0);
                asm("ex2.approx.f16x2 %0, %1;" : "=r"(P00) : "r"(d0));
                asm("ex2.approx.f16x2 %0, %1;" : "=r"(P01) : "r"(d1));
                uint32_t w = sMaskP[buf][8 * t + m];
                P00 &= w;
                P01 &= w;
                float2 fa = __half22float2(*reinterpret_cast<half2*>(&P00));
                float2 fb = __half22float2(*reinterpret_cast<half2*>(&P01));
                l_lo += fa.x + fa.y;
                l_hi += fb.x + fb.y;
            }
            {
                int key = 16 * t + 8 + r;
                uint32_t kb0 = k32[key * 4 + m];
                uint32_t d0, d1;
                mma16808h(d0, d1, a0, a1, kb0);
                asm("ex2.approx.f16x2 %0, %1;" : "=r"(P10) : "r"(d0));
                asm("ex2.approx.f16x2 %0, %1;" : "=r"(P11) : "r"(d1));
                uint32_t w = sMaskP[buf][8 * t + 4 + m];
                P10 &= w;
                P11 &= w;
                float2 fa = __half22float2(*reinterpret_cast<half2*>(&P10));
                float2 fb = __half22float2(*reinterpret_cast<half2*>(&P11));
                l_lo += fa.x + fa.y;
                l_hi += fb.x + fb.y;
            }
            uint32_t vb0 = sVT[buf][r][t * 8 + m];
            uint32_t vb1 = sVT[buf][r][t * 8 + 4 + m];
            mma16816(O, P00, P01, P10, P11, vb0, vb1, O);
        }
        __syncthreads();
    }

    l_lo += __shfl_xor_sync(0xffffffffu, l_lo, 1);
    l_lo += __shfl_xor_sync(0xffffffffu, l_lo, 2);
    l_hi += __shfl_xor_sync(0xffffffffu, l_hi, 1);
    l_hi += __shfl_xor_sync(0xffffffffu, l_hi, 2);
    float inv_lo = 1.0f / l_lo;
    float inv_hi = 1.0f / l_hi;

    const int h  = bh & 31;
    const int q0 = (qt << 7) + wid * 16 + r;
    uint32_t* op = g_attnh + ((size_t)b * SS + q0) * 128 + h * 4 + m;
    half2 o1 = __floats2half2_rn(O[0] * inv_lo, O[1] * inv_lo);
    half2 o2 = __floats2half2_rn(O[2] * inv_hi, O[3] * inv_hi);
    op[0]       = *reinterpret_cast<uint32_t*>(&o1);
    op[8 * 128] = *reinterpret_cast<uint32_t*>(&o2);
}

// ---------------------------------------------------------------------------
// Output projection via fp16 MMA: Y[4096,256] = A @ Wh^T + b.
// Tile 32(M)x64(N), K=256 staged once; A tile 16.9KB + Wh tile 33.8KB
// -> smem 50.7KB -> occ 4, grid 512 (3.5 CTAs/SM): staging latency hidden.
// ---------------------------------------------------------------------------
__global__ __launch_bounds__(256, 4) void proj_kernel(
    const float* __restrict__ bo,
    float*       __restrict__ Y)
{
    extern __shared__ uint32_t sh[];     // As: 32*132 u32, Ws: 64*132 u32
    uint32_t* As = sh;
    uint32_t* Ws = sh + 32 * 132;

    const int tid = threadIdx.x;
    const int im0 = blockIdx.x * 32;
    const int jn0 = blockIdx.y * 64;

    // Stage A (fp16): 32 rows x 128 u32 = 1024 uint4
#pragma unroll
    for (int l = 0; l < 4; l++) {
        int idx = l * 256 + tid;
        int row = idx >> 5, c4 = idx & 31;
        uint4 v = *reinterpret_cast<const uint4*>(
            g_attnh + (size_t)(im0 + row) * 128 + c4 * 4);
        *reinterpret_cast<uint4*>(As + row * 132 + c4 * 4) = v;
    }
    // Stage Wh (fp16): 64 rows x 128 u32 = 2048 uint4
#pragma unroll
    for (int l = 0; l < 8; l++) {
        int idx = l * 256 + tid;
        int row = idx >> 5, c4 = idx & 31;
        uint4 v = *reinterpret_cast<const uint4*>(
            g_wh + (size_t)(jn0 + row) * 128 + c4 * 4);
        *reinterpret_cast<uint4*>(Ws + row * 132 + c4 * 4) = v;
    }
    __syncthreads();

    const int lane = tid & 31, wid = tid >> 5;
    const int r = lane >> 2, m = lane & 3;
    const int mb  = (wid & 1) * 16;      // m-block (2)
    const int nb0 = (wid >> 1) * 16;     // 2 n8-blocks each

    float acc[2][4];
#pragma unroll
    for (int nn = 0; nn < 2; nn++)
#pragma unroll
        for (int i = 0; i < 4; i++) acc[nn][i] = 0.f;

#pragma unroll
    for (int kc = 0; kc < 16; kc++) {
        uint32_t a0 = As[(mb + r) * 132 + kc * 8 + m];
        uint32_t a1 = As[(mb + r + 8) * 132 + kc * 8 + m];
        uint32_t a2 = As[(mb + r) * 132 + kc * 8 + 4 + m];
        uint32_t a3 = As[(mb + r + 8) * 132 + kc * 8 + 4 + m];
#pragma unroll
        for (int nn = 0; nn < 2; nn++) {
            uint32_t b0 = Ws[(nb0 + nn * 8 + r) * 132 + kc * 8 + m];
            uint32_t b1 = Ws[(nb0 + nn * 8 + r) * 132 + kc * 8 + 4 + m];
            mma16816(acc[nn], a0, a1, a2, a3, b0, b1, acc[nn]);
        }
    }

    // Epilogue: bias + fp32 stores
#pragma unroll
    for (int nn = 0; nn < 2; nn++) {
        int j = jn0 + nb0 + nn * 8 + 2 * m;
        float2 bv = *reinterpret_cast<const float2*>(bo + j);
        int i0 = im0 + mb + r;
        *reinterpret_cast<float2*>(Y + (size_t)i0 * 256 + j) =
            make_float2(acc[nn][0] + bv.x, acc[nn][1] + bv.y);
        *reinterpret_cast<float2*>(Y + (size_t)(i0 + 8) * 256 + j) =
            make_float2(acc[nn][2] + bv.x, acc[nn][3] + bv.y);
    }
}

// ---------------------------------------------------------------------------
extern "C" void kernel_launch(void* const* d_in, const int* in_sizes, int n_in,
                              void* d_out, int out_size)
{
    const float* x     = (const float*)d_in[0];
    const int*   mask  = (const int*)d_in[1];
    const float* theta = (const float*)d_in[2];
    const float* W     = (const float*)d_in[3];
    const float* bo    = (const float*)d_in[4];
    float*       out   = (float*)d_out;

    prep_kernel<<<544, 256>>>(x, theta, W);
    attn_kernel<<<64 * 16, 256>>>(mask);

    const int proj_smem = (32 + 64) * 132 * 4;   // 50.7 KB
    cudaFuncSetAttribute(proj_kernel,
                         cudaFuncAttributeMaxDynamicSharedMemorySize, proj_smem);
    dim3 grid(BB * SS / 32, EE / 64);  // (128, 4)
    proj_kernel<<<grid, 256, proj_smem>>>(bo, out);
}